// round 14
// baseline (speedup 1.0000x reference)
#include <cuda_runtime.h>
#include <math.h>

// Fixed shapes: B=32, S=128, V=8, T=66 -> 256 independent sequences.
// One block (320 thr) per sequence, two disjoint 5-warp barrier DOMAINS:
//   domain 0 (warps 0-4): forward  alpha_0 -> alpha_63  (63 steps)
//   domain 1 (warps 5-9): backward w_127  -> w_64       (63 steps)
// Each domain syncs only on its own named barrier (bar.sync d+1, 160).
// Step body = half-split slots: thread = (column, row-half), 17 fma2 each.
// Meet once: Z = alpha_63^T M w_64.
#define TT   66
#define SS   128
#define NSEQ 256
#define NTHR 320
#define USTR 72

typedef unsigned long long ull;

__device__ float        g_partial[NSEQ];
__device__ unsigned int g_count = 0;

static __device__ __forceinline__ ull pk2(float lo, float hi) {
    ull r; asm("mov.b64 %0, {%1,%2};" : "=l"(r) : "f"(lo), "f"(hi)); return r;
}
static __device__ __forceinline__ void fma2(ull& d, ull a, ull b) {
    asm("fma.rn.f32x2 %0, %1, %2, %0;" : "+l"(d) : "l"(a), "l"(b));
}
static __device__ __forceinline__ void add2(ull& d, ull a, ull b) {
    asm("add.rn.f32x2 %0, %1, %2;" : "=l"(d) : "l"(a), "l"(b));
}
static __device__ __forceinline__ float2 upk2(ull v) {
    float lo, hi; asm("mov.b64 {%0,%1}, %2;" : "=f"(lo), "=f"(hi) : "l"(v));
    return make_float2(lo, hi);
}
#define DBAR(dd) asm volatile("bar.sync %0, 160;" :: "r"((dd) + 1) : "memory")

__global__ void __launch_bounds__(NTHR) crf_kernel(
    const float* __restrict__ score,       // [B,S,S,T]
    const float* __restrict__ trans,       // [T,T]
    const float* __restrict__ startT,      // [T]
    const float* __restrict__ endT,        // [T]
    const int*   __restrict__ v_label,     // [B*V]
    const int*   __restrict__ role_label,  // [B*V][S]
    float*       __restrict__ out)
{
    // u slab layout (USTR floats): [0..31]=u0..31, [36..67]=u32..63 (bank shift),
    // [68..69]=u64,u65. Writer loc for state c: c + (c>=32 ? 4 : 0).
    __shared__ __align__(16) float esh[SS*TT];        // exp(emissions), full seq
    __shared__ __align__(16) float ubuf[2][2][USTR];  // [domain][pingpong]
    __shared__ float wmax[2][5];                      // [domain][warp-in-domain]
    __shared__ float sL[2], sSc[2];
    __shared__ float sgold[4], sws[5], wred[4];
    __shared__ int   sflag;

    const int tid  = threadIdx.x;
    const int lane = tid & 31;
    const int wid  = tid >> 5;
    const int d    = (wid >= 5) ? 1 : 0;   // 0 = forward, 1 = backward
    const int ts   = tid - d*160;          // slot within domain
    const int w5   = ts >> 5;              // warp index within domain (0..4)
    const bool act = (ts < 132);
    const int cc   = act ? (ts >> 1) : 0;  // my state (column fwd / row bwd)
    const int h    = ts & 1;               // my row-half (fwd) / col-half (bwd)
    const int loc  = cc + ((cc >= 32) ? 4 : 0);
    const int seq  = blockIdx.x;
    const int vr   = __ldg(&v_label[seq]);
    const float* erow = score + ((size_t)((seq >> 3)*SS + vr))*SS*TT;

    // ---- gold path: warps 0-3, one position per thread ----
    if (tid < 128) {
        int s  = tid;
        int tg = __ldg(&role_label[seq*SS + s]);
        float gg = __ldg(&erow[s*TT + tg]);
        if (s < SS-1) gg += __ldg(&trans[tg*TT + __ldg(&role_label[seq*SS + s + 1])]);
        else          gg += __ldg(&endT[tg]);
        if (s == 0)   gg += __ldg(&startT[tg]);
        #pragma unroll
        for (int o = 16; o; o >>= 1) gg += __shfl_xor_sync(~0u, gg, o);
        if (lane == 0) sgold[wid] = gg;
    }

    // ---- stage exp(emissions) for the whole sequence (all 320 threads) ----
    {
        const float4* src = (const float4*)erow;
        float4*       dst = (float4*)esh;
        #pragma unroll 2
        for (int k = tid; k < (SS*TT)/4; k += NTHR) {
            float4 v = __ldg(&src[k]);
            v.x = __expf(v.x); v.y = __expf(v.y);
            v.z = __expf(v.z); v.w = __expf(v.w);
            dst[k] = v;
        }
    }

    // ---- exp(trans) regs: fwd = COLUMN cc over my row-half;
    //      bwd = ROW cc over my col-half. 17 packed pairs each. ----
    ull e[17];
    if (act) {
        if (d == 0) {
            #pragma unroll
            for (int k = 0; k < 16; k++) {
                int rr = h*32 + 2*k;
                e[k] = pk2(__expf(__ldg(&trans[rr*TT + cc])),
                           __expf(__ldg(&trans[(rr+1)*TT + cc])));
            }
            e[16] = (h == 0) ? pk2(__expf(__ldg(&trans[64*TT + cc])),
                                   __expf(__ldg(&trans[65*TT + cc]))) : 0ULL;
        } else {
            #pragma unroll
            for (int k = 0; k < 16; k++) {
                float2 f = __ldg((const float2*)(trans + cc*TT + h*32 + 2*k));
                e[k] = pk2(__expf(f.x), __expf(f.y));
            }
            if (h == 0) {
                float2 f = __ldg((const float2*)(trans + cc*TT + 64));
                e[16] = pk2(__expf(f.x), __expf(f.y));
            } else e[16] = 0ULL;
        }
    } else {
        #pragma unroll
        for (int k = 0; k < 17; k++) e[k] = 0ULL;
    }
    const float bis = act ? __expf(__ldg(d ? &endT[cc] : &startT[cc])) : 0.f;

    __syncthreads();   // esh staged

    // ---- init: fwd alpha_0 = exp(start)*e_0 ; bwd w_127 = exp(end)*e_127 ----
    const float* e0row = esh + (d ? 127*TT : 0);
    float r = act ? (bis * e0row[cc]) : 0.f;
    if (act && h == 0) ubuf[d][0][loc] = r;
    {
        float mm = r;
        #pragma unroll
        for (int o = 16; o; o >>= 1) mm = fmaxf(mm, __shfl_xor_sync(~0u, mm, o));
        if (lane == 0) wmax[d][w5] = mm;
    }
    DBAR(d);
    float m  = fmaxf(fmaxf(fmaxf(wmax[d][0], wmax[d][1]),
                           fmaxf(wmax[d][2], wmax[d][3])), wmax[d][4]);
    float sc = __fdividef(1.0f, m);
    float L  = __logf(m);

    float* uc = ubuf[d][0];
    float* un = ubuf[d][1];
    const int dE = d ? -TT : TT;
    const float* emrow = esh + (d ? 126*TT : TT);

    // ---- one step: half-dot per thread + pair-shfl combine; domain barrier ----
    auto STEP = [&](float scale, bool renorm) {
        float em = emrow[cc];
        const ulonglong2* u2 = (const ulonglong2*)(uc + h*36);  // h=0:+0B, h=1:+144B
        ull d0 = 0, d1 = 0;
        #pragma unroll
        for (int i = 0; i < 8; i++) {
            ulonglong2 v = u2[i];
            fma2(d0, v.x, e[2*i]);
            fma2(d1, v.y, e[2*i+1]);
        }
        ull lastp = *(const ull*)(uc + 68);    // (u64, u65)
        fma2(d0, lastp, e[16]);                // h=1 contributes 0
        add2(d0, d0, d1);
        float2 f = upk2(d0);
        float s = f.x + f.y;
        s += __shfl_xor_sync(~0u, s, 1);       // combine the two halves
        r = act ? s * (scale * em) : 0.f;
        if (act && h == 0) un[loc] = r;
        if (renorm) {
            float mm = r;
            #pragma unroll
            for (int o = 16; o; o >>= 1) mm = fmaxf(mm, __shfl_xor_sync(~0u, mm, o));
            if (lane == 0) wmax[d][w5] = mm;
        }
        DBAR(d);
        float* tp = uc; uc = un; un = tp;
        emrow += dE;
    };

    // ---- 63 steps: 7 groups of 8 + tail 7; renorm at group ends ----
    for (int grp = 0; grp < 8; grp++) {
        const int n = (grp == 7) ? 7 : 8;
        #pragma unroll 8
        for (int q = 0; q < n; q++) STEP((q == 0) ? sc : 1.0f, q == n-1);
        m  = fmaxf(fmaxf(fmaxf(wmax[d][0], wmax[d][1]),
                         fmaxf(wmax[d][2], wmax[d][3])), wmax[d][4]);
        sc = __fdividef(1.0f, m);
        L += __logf(m);
    }
    // invariant: actual = stored * exp(L) * sc   (sc pending)

    if (ts == 0) { sL[d] = L; sSc[d] = sc; }
    __syncthreads();   // domains meet; final slabs + scales visible

    // ---- epilogue (domain 0): Z = sum_c (M^T alpha_63)_c * w_64[c] ----
    if (d == 0) {
        const ulonglong2* u2 = (const ulonglong2*)(uc + h*36);
        ull d0 = 0, d1 = 0;
        #pragma unroll
        for (int i = 0; i < 8; i++) {
            ulonglong2 v = u2[i];
            fma2(d0, v.x, e[2*i]);
            fma2(d1, v.y, e[2*i+1]);
        }
        ull lastp = *(const ull*)(uc + 68);
        fma2(d0, lastp, e[16]);
        add2(d0, d0, d1);
        float2 f = upk2(d0);
        float s = f.x + f.y;
        s += __shfl_xor_sync(~0u, s, 1);
        float contrib = 0.f;
        if (act && h == 0) {
            float wv = ubuf[1][1][loc];        // w_64 stored (63 steps end in slab 1)
            contrib = (s * sc) * (wv * sSc[1]);
        }
        #pragma unroll
        for (int o = 16; o; o >>= 1) contrib += __shfl_xor_sync(~0u, contrib, o);
        if (lane == 0) sws[w5] = contrib;
    }
    __syncthreads();

    if (tid == 0) {
        float ws = (((sws[0] + sws[1]) + (sws[2] + sws[3])) + sws[4]);
        float gt = (sgold[0] + sgold[1]) + (sgold[2] + sgold[3]);
        __stcg(&g_partial[seq], __logf(ws) + sL[0] + sL[1] - gt);
        __threadfence();
        unsigned c0 = atomicAdd(&g_count, 1u);
        sflag = (c0 == NSEQ - 1) ? 1 : 0;
    }
    __syncthreads();

    // ---- fused final reduction in the last block ----
    if (sflag) {
        if (tid < 128) {
            float v = __ldcg(&g_partial[tid]) + __ldcg(&g_partial[tid + 128]);
            #pragma unroll
            for (int o = 16; o; o >>= 1) v += __shfl_xor_sync(~0u, v, o);
            if (lane == 0) wred[wid] = v;
        }
        __syncthreads();
        if (tid == 0) {
            out[0] = ((wred[0] + wred[1]) + (wred[2] + wred[3]))
                     * (1.0f / (float)NSEQ);
            g_count = 0;                       // reset for next graph replay
        }
    }
}

extern "C" void kernel_launch(void* const* d_in, const int* in_sizes, int n_in,
                              void* d_out, int out_size) {
    const float* score      = (const float*)d_in[0];
    const float* trans      = (const float*)d_in[1];
    const float* startT     = (const float*)d_in[2];
    const float* endT       = (const float*)d_in[3];
    const int*   v_label    = (const int*)d_in[4];
    const int*   role_label = (const int*)d_in[5];
    float* out = (float*)d_out;

    crf_kernel<<<NSEQ, NTHR>>>(score, trans, startT, endT, v_label, role_label, out);
}